// round 1
// baseline (speedup 1.0000x reference)
#include <cuda_runtime.h>
#include <cstddef>

#define B_  2
#define S_  2048
#define H_  1024
#define NH_ 16
#define HD_ 64
#define M_  (B_ * S_)   // 4096 rows

// Scratch (allocation-free rule: __device__ globals)
__device__ float g_Q[(size_t)M_ * H_];
__device__ float g_K[(size_t)M_ * H_];
__device__ float g_V[(size_t)M_ * H_];
__device__ float g_AO[(size_t)M_ * H_];

// ---------------------------------------------------------------------------
// C[M,N] = X[M,K] @ W[N,K]^T + bias   (torch Linear), fp32, 128x128x8 tiles
// ---------------------------------------------------------------------------
__global__ __launch_bounds__(256, 2)
void gemm_bias_kernel(const float* __restrict__ X, const float* __restrict__ W,
                      const float* __restrict__ bias, float* __restrict__ C,
                      int Kd, int Nd)
{
    __shared__ float As[8 * 132];   // [k][m], padded
    __shared__ float Bs[8 * 132];   // [k][n], padded

    const int tid = threadIdx.x;
    const int m0  = blockIdx.y * 128;
    const int n0  = blockIdx.x * 128;
    const int lm  = tid >> 1;            // 0..127
    const int lk  = (tid & 1) << 2;      // 0 or 4
    const int ty4 = (tid >> 4) << 2;     // row sub-offset
    const int tx4 = (tid & 15) << 2;     // col sub-offset

    float acc[8][8];
#pragma unroll
    for (int i = 0; i < 8; ++i)
#pragma unroll
        for (int j = 0; j < 8; ++j) acc[i][j] = 0.0f;

    const float* Ap = X + (size_t)(m0 + lm) * Kd + lk;
    const float* Bp = W + (size_t)(n0 + lm) * Kd + lk;

    for (int kt = 0; kt < Kd; kt += 8) {
        float4 av = *(const float4*)(Ap + kt);
        float4 bv = *(const float4*)(Bp + kt);
        __syncthreads();
        As[(lk + 0) * 132 + lm] = av.x;
        As[(lk + 1) * 132 + lm] = av.y;
        As[(lk + 2) * 132 + lm] = av.z;
        As[(lk + 3) * 132 + lm] = av.w;
        Bs[(lk + 0) * 132 + lm] = bv.x;
        Bs[(lk + 1) * 132 + lm] = bv.y;
        Bs[(lk + 2) * 132 + lm] = bv.z;
        Bs[(lk + 3) * 132 + lm] = bv.w;
        __syncthreads();
#pragma unroll
        for (int kk = 0; kk < 8; ++kk) {
            float4 a0 = *(const float4*)&As[kk * 132 + ty4];
            float4 a1 = *(const float4*)&As[kk * 132 + 64 + ty4];
            float4 b0 = *(const float4*)&Bs[kk * 132 + tx4];
            float4 b1 = *(const float4*)&Bs[kk * 132 + 64 + tx4];
            float a[8]  = {a0.x, a0.y, a0.z, a0.w, a1.x, a1.y, a1.z, a1.w};
            float bb[8] = {b0.x, b0.y, b0.z, b0.w, b1.x, b1.y, b1.z, b1.w};
#pragma unroll
            for (int i = 0; i < 8; ++i)
#pragma unroll
                for (int j = 0; j < 8; ++j)
                    acc[i][j] = fmaf(a[i], bb[j], acc[i][j]);
        }
    }

#pragma unroll
    for (int i = 0; i < 8; ++i) {
        int r = m0 + ((i < 4) ? (ty4 + i) : (64 + ty4 + i - 4));
        float* cp = C + (size_t)r * Nd + n0;
        float4 o0, o1;
        o0.x = acc[i][0] + bias[n0 + tx4 + 0];
        o0.y = acc[i][1] + bias[n0 + tx4 + 1];
        o0.z = acc[i][2] + bias[n0 + tx4 + 2];
        o0.w = acc[i][3] + bias[n0 + tx4 + 3];
        o1.x = acc[i][4] + bias[n0 + 64 + tx4 + 0];
        o1.y = acc[i][5] + bias[n0 + 64 + tx4 + 1];
        o1.z = acc[i][6] + bias[n0 + 64 + tx4 + 2];
        o1.w = acc[i][7] + bias[n0 + 64 + tx4 + 3];
        *(float4*)(cp + tx4)      = o0;
        *(float4*)(cp + 64 + tx4) = o1;
    }
}

// ---------------------------------------------------------------------------
// Flash attention: Q-tile 128 x HD64, KV-tile 64. Online softmax entirely in
// registers (per-row stats replicated across the 16-lane half-warp that owns
// those rows; combined via __shfl_xor_sync).
// scores = (Q K^T)/8 * script_mask; mask==0 -> -1e30; softmax; @ V
// ---------------------------------------------------------------------------
#define ATT_SMEM_FLOATS (64 * 132 + 64 * 68 + 64 * 132 + 64 * 64)
#define ATT_SMEM_BYTES  (ATT_SMEM_FLOATS * 4)

__global__ __launch_bounds__(256, 2)
void attn_kernel(const float* __restrict__ Qg, const float* __restrict__ Kg,
                 const float* __restrict__ Vg, const int* __restrict__ maskg,
                 const float* __restrict__ smg, float* __restrict__ Og)
{
    extern __shared__ float smem[];
    float* Qs = smem;                    // [d=64][r=128+pad4]  d-major
    float* Ks = Qs + 64 * 132;           // [d=64][c=64+pad4]   d-major
    float* Ps = Ks + 64 * 68;            // [j=64][r=128+pad4]  j-major
    float* Vs = Ps + 64 * 132;           // [j=64][c=64]        natural

    const int tid = threadIdx.x;
    const int q0  = blockIdx.x * 128;
    const int h   = blockIdx.y;
    const int b   = blockIdx.z;
    const int ty4 = (tid >> 4) << 2;
    const int tx4 = (tid & 15) << 2;

    const size_t qkv_base = (size_t)b * S_ * H_ + (size_t)h * HD_;

    // Load Q tile, transposed to d-major
    for (int i = tid; i < 128 * 16; i += 256) {
        int r  = i >> 4;
        int dq = (i & 15) << 2;
        float4 q4 = *(const float4*)&Qg[qkv_base + (size_t)(q0 + r) * H_ + dq];
        Qs[(dq + 0) * 132 + r] = q4.x;
        Qs[(dq + 1) * 132 + r] = q4.y;
        Qs[(dq + 2) * 132 + r] = q4.z;
        Qs[(dq + 3) * 132 + r] = q4.w;
    }

    float acc[8][4];
    float m_i[8], l_i[8];
#pragma unroll
    for (int i = 0; i < 8; ++i) {
        m_i[i] = -1e30f;
        l_i[i] = 0.0f;
#pragma unroll
        for (int j = 0; j < 4; ++j) acc[i][j] = 0.0f;
    }

    const float scale = 0.125f;  // 1/sqrt(64)

    for (int k0 = 0; k0 < S_; k0 += 64) {
        __syncthreads();  // previous P@V done before overwriting tiles
        // Load K (transposed to d-major) and V (natural) tiles
        for (int i = tid; i < 64 * 16; i += 256) {
            int row = i >> 4;
            int dq  = (i & 15) << 2;
            size_t g = qkv_base + (size_t)(k0 + row) * H_ + dq;
            float4 k4 = *(const float4*)&Kg[g];
            Ks[(dq + 0) * 68 + row] = k4.x;
            Ks[(dq + 1) * 68 + row] = k4.y;
            Ks[(dq + 2) * 68 + row] = k4.z;
            Ks[(dq + 3) * 68 + row] = k4.w;
            float4 v4 = *(const float4*)&Vg[g];
            *(float4*)&Vs[row * 64 + dq] = v4;
        }
        __syncthreads();

        // S = Q K^T (128 x 64 tile, 8x4 per thread)
        float sv[8][4];
#pragma unroll
        for (int i = 0; i < 8; ++i)
#pragma unroll
            for (int j = 0; j < 4; ++j) sv[i][j] = 0.0f;

#pragma unroll 16
        for (int d = 0; d < 64; ++d) {
            float4 a0 = *(const float4*)&Qs[d * 132 + ty4];
            float4 a1 = *(const float4*)&Qs[d * 132 + 64 + ty4];
            float4 bk = *(const float4*)&Ks[d * 68 + tx4];
            float a[8]  = {a0.x, a0.y, a0.z, a0.w, a1.x, a1.y, a1.z, a1.w};
            float bb[4] = {bk.x, bk.y, bk.z, bk.w};
#pragma unroll
            for (int i = 0; i < 8; ++i)
#pragma unroll
                for (int j = 0; j < 4; ++j)
                    sv[i][j] = fmaf(a[i], bb[j], sv[i][j]);
        }

        // masks + online softmax (stats replicated across half-warp)
        float alpha[8];
#pragma unroll
        for (int i = 0; i < 8; ++i) {
            int r  = (i < 4) ? (ty4 + i) : (64 + ty4 + i - 4);
            int qg = q0 + r;
            size_t mrow = ((size_t)b * S_ + qg) * S_ + k0 + tx4;
            float4 sm4 = *(const float4*)&smg[mrow];
            int4   mk  = *(const int4*)&maskg[mrow];
            float s0 = sv[i][0] * scale * sm4.x; if (mk.x == 0) s0 = -1e30f;
            float s1 = sv[i][1] * scale * sm4.y; if (mk.y == 0) s1 = -1e30f;
            float s2 = sv[i][2] * scale * sm4.z; if (mk.z == 0) s2 = -1e30f;
            float s3 = sv[i][3] * scale * sm4.w; if (mk.w == 0) s3 = -1e30f;

            float tmax = fmaxf(fmaxf(s0, s1), fmaxf(s2, s3));
            tmax = fmaxf(tmax, __shfl_xor_sync(0xffffffffu, tmax, 1));
            tmax = fmaxf(tmax, __shfl_xor_sync(0xffffffffu, tmax, 2));
            tmax = fmaxf(tmax, __shfl_xor_sync(0xffffffffu, tmax, 4));
            tmax = fmaxf(tmax, __shfl_xor_sync(0xffffffffu, tmax, 8));

            float newm = fmaxf(m_i[i], tmax);
            alpha[i] = __expf(m_i[i] - newm);
            m_i[i] = newm;

            float p0 = __expf(s0 - newm);
            float p1 = __expf(s1 - newm);
            float p2 = __expf(s2 - newm);
            float p3 = __expf(s3 - newm);
            float rsum = (p0 + p1) + (p2 + p3);
            rsum += __shfl_xor_sync(0xffffffffu, rsum, 1);
            rsum += __shfl_xor_sync(0xffffffffu, rsum, 2);
            rsum += __shfl_xor_sync(0xffffffffu, rsum, 4);
            rsum += __shfl_xor_sync(0xffffffffu, rsum, 8);
            l_i[i] = l_i[i] * alpha[i] + rsum;
            sv[i][0] = p0; sv[i][1] = p1; sv[i][2] = p2; sv[i][3] = p3;
        }

        // Write P transposed: Ps[j][r]
#pragma unroll
        for (int jj = 0; jj < 4; ++jj) {
            float4 lo = make_float4(sv[0][jj], sv[1][jj], sv[2][jj], sv[3][jj]);
            float4 hi = make_float4(sv[4][jj], sv[5][jj], sv[6][jj], sv[7][jj]);
            *(float4*)&Ps[(tx4 + jj) * 132 + ty4]      = lo;
            *(float4*)&Ps[(tx4 + jj) * 132 + 64 + ty4] = hi;
        }
        __syncthreads();

        // acc = acc*alpha + P @ V
#pragma unroll
        for (int i = 0; i < 8; ++i) {
            float al = alpha[i];
#pragma unroll
            for (int j = 0; j < 4; ++j) acc[i][j] *= al;
        }
#pragma unroll 8
        for (int j = 0; j < 64; ++j) {
            float4 p0 = *(const float4*)&Ps[j * 132 + ty4];
            float4 p1 = *(const float4*)&Ps[j * 132 + 64 + ty4];
            float4 vv = *(const float4*)&Vs[j * 64 + tx4];
            float pr[8] = {p0.x, p0.y, p0.z, p0.w, p1.x, p1.y, p1.z, p1.w};
            float vc[4] = {vv.x, vv.y, vv.z, vv.w};
#pragma unroll
            for (int i = 0; i < 8; ++i)
#pragma unroll
                for (int c = 0; c < 4; ++c)
                    acc[i][c] = fmaf(pr[i], vc[c], acc[i][c]);
        }
    }

    // Epilogue: divide by l, write [B,S,H] layout
#pragma unroll
    for (int i = 0; i < 8; ++i) {
        int r = (i < 4) ? (ty4 + i) : (64 + ty4 + i - 4);
        float inv = 1.0f / l_i[i];
        float4 o = make_float4(acc[i][0] * inv, acc[i][1] * inv,
                               acc[i][2] * inv, acc[i][3] * inv);
        *(float4*)&Og[qkv_base + (size_t)(q0 + r) * H_ + tx4] = o;
    }
}

// ---------------------------------------------------------------------------
extern "C" void kernel_launch(void* const* d_in, const int* in_sizes, int n_in,
                              void* d_out, int out_size)
{
    const float* query = (const float*)d_in[0];
    const float* key   = (const float*)d_in[1];
    const float* value = (const float*)d_in[2];
    const int*   mask  = (const int*)d_in[3];
    const float* smask = (const float*)d_in[4];
    const float* Wq = (const float*)d_in[5];
    const float* bq = (const float*)d_in[6];
    const float* Wk = (const float*)d_in[7];
    const float* bk = (const float*)d_in[8];
    const float* Wv = (const float*)d_in[9];
    const float* bv = (const float*)d_in[10];
    const float* Wo = (const float*)d_in[11];
    const float* bo = (const float*)d_in[12];
    float* out = (float*)d_out;

    float *gq, *gk, *gv, *gao;
    cudaGetSymbolAddress((void**)&gq,  g_Q);
    cudaGetSymbolAddress((void**)&gk,  g_K);
    cudaGetSymbolAddress((void**)&gv,  g_V);
    cudaGetSymbolAddress((void**)&gao, g_AO);

    cudaFuncSetAttribute(attn_kernel,
                         cudaFuncAttributeMaxDynamicSharedMemorySize,
                         ATT_SMEM_BYTES);

    dim3 gblk(256);
    dim3 ggrid(H_ / 128, M_ / 128);   // (8, 32)
    gemm_bias_kernel<<<ggrid, gblk>>>(query, Wq, bq, gq, H_, H_);
    gemm_bias_kernel<<<ggrid, gblk>>>(key,   Wk, bk, gk, H_, H_);
    gemm_bias_kernel<<<ggrid, gblk>>>(value, Wv, bv, gv, H_, H_);

    dim3 agrid(S_ / 128, NH_, B_);    // (16, 16, 2)
    attn_kernel<<<agrid, 256, ATT_SMEM_BYTES>>>(gq, gk, gv, mask, smask, gao);

    gemm_bias_kernel<<<ggrid, gblk>>>(gao, Wo, bo, out, H_, H_);
}

// round 3
// speedup vs baseline: 1.3784x; 1.3784x over previous
#include <cuda_runtime.h>
#include <cstdint>
#include <cstddef>

#define B_  2
#define S_  2048
#define H_  1024
#define NH_ 16
#define HD_ 64
#define M_  (B_ * S_)   // 4096 rows

// Scratch (allocation-free rule: __device__ globals)
__device__ float g_Q[(size_t)M_ * H_];
__device__ float g_K[(size_t)M_ * H_];
__device__ float g_V[(size_t)M_ * H_];
__device__ float g_AO[(size_t)M_ * H_];

// ---------------------------------------------------------------------------
// tf32 helpers
// ---------------------------------------------------------------------------
__device__ __forceinline__ uint32_t f32_to_tf32(float x) {
    uint32_t u;
    asm("cvt.rna.tf32.f32 %0, %1;" : "=r"(u) : "f"(x));
    return u;
}

__device__ __forceinline__ void mma_tf32(float& d0, float& d1, float& d2, float& d3,
                                         uint32_t a0, uint32_t a1, uint32_t a2, uint32_t a3,
                                         uint32_t b0, uint32_t b1) {
    asm volatile(
        "mma.sync.aligned.m16n8k8.row.col.f32.tf32.tf32.f32 "
        "{%0,%1,%2,%3}, {%4,%5,%6,%7}, {%8,%9}, {%0,%1,%2,%3};"
        : "+f"(d0), "+f"(d1), "+f"(d2), "+f"(d3)
        : "r"(a0), "r"(a1), "r"(a2), "r"(a3), "r"(b0), "r"(b1));
}

// ===========================================================================
// tf32 mma.sync GEMM: C[M,N] = X[M,K] @ W[N,K]^T + bias  (M=4096, N=K=1024)
// CTA tile 128x128, 8 warps (warp tile 64x32), K chunk 16, reg-prefetch.
// SMEM layout: As[m][k] / Bs[n][k], row pad 20 floats (conflict-free frags).
// ===========================================================================
#define PAD_ 20

__global__ __launch_bounds__(256, 2)
void gemm_mma_kernel(const float* __restrict__ X, const float* __restrict__ W,
                     const float* __restrict__ bias, float* __restrict__ C)
{
    __shared__ float As[128 * PAD_];
    __shared__ float Bs[128 * PAD_];

    const int tid  = threadIdx.x;
    const int wid  = tid >> 5;
    const int lane = tid & 31;
    const int m0   = blockIdx.y * 128;
    const int n0   = blockIdx.x * 128;
    const int warp_m = (wid & 1) * 64;
    const int warp_n = (wid >> 1) * 32;
    const int qrow = lane >> 2;   // 0..7
    const int qcol = lane & 3;    // 0..3

    // global-load mapping: float4 i covers row=i>>2, cols (i&3)*4..+3 of chunk
    const int r0 = tid >> 2;              // i0 = tid
    const int c0 = (tid & 3) * 4;
    const int r1 = (tid + 256) >> 2;      // i1 = tid + 256
    const int c1 = ((tid + 256) & 3) * 4;

    const float* Xa0 = X + (size_t)(m0 + r0) * H_ + c0;
    const float* Xa1 = X + (size_t)(m0 + r1) * H_ + c1;
    const float* Wb0 = W + (size_t)(n0 + r0) * H_ + c0;
    const float* Wb1 = W + (size_t)(n0 + r1) * H_ + c1;

    float acc[16][4];
#pragma unroll
    for (int i = 0; i < 16; ++i)
#pragma unroll
        for (int j = 0; j < 4; ++j) acc[i][j] = 0.0f;

    float4 ra0 = *(const float4*)Xa0;
    float4 ra1 = *(const float4*)Xa1;
    float4 rb0 = *(const float4*)Wb0;
    float4 rb1 = *(const float4*)Wb1;

    const int NCHUNK = H_ / 16;  // 64

    for (int c = 0; c < NCHUNK; ++c) {
        if (c > 0) __syncthreads();
        // store (convert to tf32 bit pattern; keep as float bits in smem)
        {
            float4 ta0 = ra0, ta1 = ra1, tb0 = rb0, tb1 = rb1;
            uint32_t* as0 = (uint32_t*)&As[r0 * PAD_ + c0];
            uint32_t* as1 = (uint32_t*)&As[r1 * PAD_ + c1];
            uint32_t* bs0 = (uint32_t*)&Bs[r0 * PAD_ + c0];
            uint32_t* bs1 = (uint32_t*)&Bs[r1 * PAD_ + c1];
            uint4 ua0 = make_uint4(f32_to_tf32(ta0.x), f32_to_tf32(ta0.y),
                                   f32_to_tf32(ta0.z), f32_to_tf32(ta0.w));
            uint4 ua1 = make_uint4(f32_to_tf32(ta1.x), f32_to_tf32(ta1.y),
                                   f32_to_tf32(ta1.z), f32_to_tf32(ta1.w));
            uint4 ub0 = make_uint4(f32_to_tf32(tb0.x), f32_to_tf32(tb0.y),
                                   f32_to_tf32(tb0.z), f32_to_tf32(tb0.w));
            uint4 ub1 = make_uint4(f32_to_tf32(tb1.x), f32_to_tf32(tb1.y),
                                   f32_to_tf32(tb1.z), f32_to_tf32(tb1.w));
            *(uint4*)as0 = ua0;
            *(uint4*)as1 = ua1;
            *(uint4*)bs0 = ub0;
            *(uint4*)bs1 = ub1;
        }
        __syncthreads();

        // prefetch next chunk
        if (c + 1 < NCHUNK) {
            int k0 = (c + 1) * 16;
            ra0 = *(const float4*)(Xa0 + k0);
            ra1 = *(const float4*)(Xa1 + k0);
            rb0 = *(const float4*)(Wb0 + k0);
            rb1 = *(const float4*)(Wb1 + k0);
        }

        // compute: 2 k-steps of 8
#pragma unroll
        for (int ks = 0; ks < 2; ++ks) {
            const int kk = ks * 8;
            uint32_t af[4][4];
            uint32_t bf[4][2];
#pragma unroll
            for (int mt = 0; mt < 4; ++mt) {
                const float* ap = &As[(warp_m + mt * 16 + qrow) * PAD_ + kk + qcol];
                af[mt][0] = __float_as_uint(ap[0]);
                af[mt][1] = __float_as_uint(ap[8 * PAD_]);
                af[mt][2] = __float_as_uint(ap[4]);
                af[mt][3] = __float_as_uint(ap[8 * PAD_ + 4]);
            }
#pragma unroll
            for (int nt = 0; nt < 4; ++nt) {
                const float* bp = &Bs[(warp_n + nt * 8 + qrow) * PAD_ + kk + qcol];
                bf[nt][0] = __float_as_uint(bp[0]);
                bf[nt][1] = __float_as_uint(bp[4]);
            }
#pragma unroll
            for (int mt = 0; mt < 4; ++mt)
#pragma unroll
                for (int nt = 0; nt < 4; ++nt)
                    mma_tf32(acc[mt * 4 + nt][0], acc[mt * 4 + nt][1],
                             acc[mt * 4 + nt][2], acc[mt * 4 + nt][3],
                             af[mt][0], af[mt][1], af[mt][2], af[mt][3],
                             bf[nt][0], bf[nt][1]);
        }
    }

    // epilogue: C[m][n] fragment layout: rows qrow,+8; cols 2*qcol,+1
#pragma unroll
    for (int mt = 0; mt < 4; ++mt) {
        int row = m0 + warp_m + mt * 16 + qrow;
#pragma unroll
        for (int nt = 0; nt < 4; ++nt) {
            int col = n0 + warp_n + nt * 8 + 2 * qcol;
            float b0v = bias[col];
            float b1v = bias[col + 1];
            float* cp0 = C + (size_t)row * H_ + col;
            float* cp1 = C + (size_t)(row + 8) * H_ + col;
            *(float2*)cp0 = make_float2(acc[mt * 4 + nt][0] + b0v,
                                        acc[mt * 4 + nt][1] + b1v);
            *(float2*)cp1 = make_float2(acc[mt * 4 + nt][2] + b0v,
                                        acc[mt * 4 + nt][3] + b1v);
        }
    }
}

// ===========================================================================
// Flash attention (unchanged from R1): Q-tile 128, KV-tile 64, fp32 SIMT
// ===========================================================================
#define ATT_SMEM_FLOATS (64 * 132 + 64 * 68 + 64 * 132 + 64 * 64)
#define ATT_SMEM_BYTES  (ATT_SMEM_FLOATS * 4)

__global__ __launch_bounds__(256, 2)
void attn_kernel(const float* __restrict__ Qg, const float* __restrict__ Kg,
                 const float* __restrict__ Vg, const int* __restrict__ maskg,
                 const float* __restrict__ smg, float* __restrict__ Og)
{
    extern __shared__ float smemf[];
    float* Qs = smemf;                   // [d=64][r=128+pad4]  d-major
    float* Ks = Qs + 64 * 132;           // [d=64][c=64+pad4]   d-major
    float* Ps = Ks + 64 * 68;            // [j=64][r=128+pad4]  j-major
    float* Vs = Ps + 64 * 132;           // [j=64][c=64]        natural

    const int tid = threadIdx.x;
    const int q0  = blockIdx.x * 128;
    const int h   = blockIdx.y;
    const int b   = blockIdx.z;
    const int ty4 = (tid >> 4) << 2;
    const int tx4 = (tid & 15) << 2;

    const size_t qkv_base = (size_t)b * S_ * H_ + (size_t)h * HD_;

    for (int i = tid; i < 128 * 16; i += 256) {
        int r  = i >> 4;
        int dq = (i & 15) << 2;
        float4 q4 = *(const float4*)&Qg[qkv_base + (size_t)(q0 + r) * H_ + dq];
        Qs[(dq + 0) * 132 + r] = q4.x;
        Qs[(dq + 1) * 132 + r] = q4.y;
        Qs[(dq + 2) * 132 + r] = q4.z;
        Qs[(dq + 3) * 132 + r] = q4.w;
    }

    float acc[8][4];
    float m_i[8], l_i[8];
#pragma unroll
    for (int i = 0; i < 8; ++i) {
        m_i[i] = -1e30f;
        l_i[i] = 0.0f;
#pragma unroll
        for (int j = 0; j < 4; ++j) acc[i][j] = 0.0f;
    }

    const float scale = 0.125f;

    for (int k0 = 0; k0 < S_; k0 += 64) {
        __syncthreads();
        for (int i = tid; i < 64 * 16; i += 256) {
            int row = i >> 4;
            int dq  = (i & 15) << 2;
            size_t g = qkv_base + (size_t)(k0 + row) * H_ + dq;
            float4 k4 = *(const float4*)&Kg[g];
            Ks[(dq + 0) * 68 + row] = k4.x;
            Ks[(dq + 1) * 68 + row] = k4.y;
            Ks[(dq + 2) * 68 + row] = k4.z;
            Ks[(dq + 3) * 68 + row] = k4.w;
            float4 v4 = *(const float4*)&Vg[g];
            *(float4*)&Vs[row * 64 + dq] = v4;
        }
        __syncthreads();

        float sv[8][4];
#pragma unroll
        for (int i = 0; i < 8; ++i)
#pragma unroll
            for (int j = 0; j < 4; ++j) sv[i][j] = 0.0f;

#pragma unroll 16
        for (int d = 0; d < 64; ++d) {
            float4 a0 = *(const float4*)&Qs[d * 132 + ty4];
            float4 a1 = *(const float4*)&Qs[d * 132 + 64 + ty4];
            float4 bk = *(const float4*)&Ks[d * 68 + tx4];
            float a[8]  = {a0.x, a0.y, a0.z, a0.w, a1.x, a1.y, a1.z, a1.w};
            float bb[4] = {bk.x, bk.y, bk.z, bk.w};
#pragma unroll
            for (int i = 0; i < 8; ++i)
#pragma unroll
                for (int j = 0; j < 4; ++j)
                    sv[i][j] = fmaf(a[i], bb[j], sv[i][j]);
        }

        float alpha[8];
#pragma unroll
        for (int i = 0; i < 8; ++i) {
            int r  = (i < 4) ? (ty4 + i) : (64 + ty4 + i - 4);
            int qg = q0 + r;
            size_t mrow = ((size_t)b * S_ + qg) * S_ + k0 + tx4;
            float4 sm4 = *(const float4*)&smg[mrow];
            int4   mk  = *(const int4*)&maskg[mrow];
            float s0 = sv[i][0] * scale * sm4.x; if (mk.x == 0) s0 = -1e30f;
            float s1 = sv[i][1] * scale * sm4.y; if (mk.y == 0) s1 = -1e30f;
            float s2 = sv[i][2] * scale * sm4.z; if (mk.z == 0) s2 = -1e30f;
            float s3 = sv[i][3] * scale * sm4.w; if (mk.w == 0) s3 = -1e30f;

            float tmax = fmaxf(fmaxf(s0, s1), fmaxf(s2, s3));
            tmax = fmaxf(tmax, __shfl_xor_sync(0xffffffffu, tmax, 1));
            tmax = fmaxf(tmax, __shfl_xor_sync(0xffffffffu, tmax, 2));
            tmax = fmaxf(tmax, __shfl_xor_sync(0xffffffffu, tmax, 4));
            tmax = fmaxf(tmax, __shfl_xor_sync(0xffffffffu, tmax, 8));

            float newm = fmaxf(m_i[i], tmax);
            alpha[i] = __expf(m_i[i] - newm);
            m_i[i] = newm;

            float p0 = __expf(s0 - newm);
            float p1 = __expf(s1 - newm);
            float p2 = __expf(s2 - newm);
            float p3 = __expf(s3 - newm);
            float rsum = (p0 + p1) + (p2 + p3);
            rsum += __shfl_xor_sync(0xffffffffu, rsum, 1);
            rsum += __shfl_xor_sync(0xffffffffu, rsum, 2);
            rsum += __shfl_xor_sync(0xffffffffu, rsum, 4);
            rsum += __shfl_xor_sync(0xffffffffu, rsum, 8);
            l_i[i] = l_i[i] * alpha[i] + rsum;
            sv[i][0] = p0; sv[i][1] = p1; sv[i][2] = p2; sv[i][3] = p3;
        }

#pragma unroll
        for (int jj = 0; jj < 4; ++jj) {
            float4 lo = make_float4(sv[0][jj], sv[1][jj], sv[2][jj], sv[3][jj]);
            float4 hi = make_float4(sv[4][jj], sv[5][jj], sv[6][jj], sv[7][jj]);
            *(float4*)&Ps[(tx4 + jj) * 132 + ty4]      = lo;
            *(float4*)&Ps[(tx4 + jj) * 132 + 64 + ty4] = hi;
        }
        __syncthreads();

#pragma unroll
        for (int i = 0; i < 8; ++i) {
            float al = alpha[i];
#pragma unroll
            for (int j = 0; j < 4; ++j) acc[i][j] *= al;
        }
#pragma unroll 8
        for (int j = 0; j < 64; ++j) {
            float4 p0 = *(const float4*)&Ps[j * 132 + ty4];
            float4 p1 = *(const float4*)&Ps[j * 132 + 64 + ty4];
            float4 vv = *(const float4*)&Vs[j * 64 + tx4];
            float pr[8] = {p0.x, p0.y, p0.z, p0.w, p1.x, p1.y, p1.z, p1.w};
            float vc[4] = {vv.x, vv.y, vv.z, vv.w};
#pragma unroll
            for (int i = 0; i < 8; ++i)
#pragma unroll
                for (int c = 0; c < 4; ++c)
                    acc[i][c] = fmaf(pr[i], vc[c], acc[i][c]);
        }
    }

#pragma unroll
    for (int i = 0; i < 8; ++i) {
        int r = (i < 4) ? (ty4 + i) : (64 + ty4 + i - 4);
        float inv = 1.0f / l_i[i];
        float4 o = make_float4(acc[i][0] * inv, acc[i][1] * inv,
                               acc[i][2] * inv, acc[i][3] * inv);
        *(float4*)&Og[qkv_base + (size_t)(q0 + r) * H_ + tx4] = o;
    }
}

// ---------------------------------------------------------------------------
extern "C" void kernel_launch(void* const* d_in, const int* in_sizes, int n_in,
                              void* d_out, int out_size)
{
    const float* query = (const float*)d_in[0];
    const float* key   = (const float*)d_in[1];
    const float* value = (const float*)d_in[2];
    const int*   mask  = (const int*)d_in[3];
    const float* smask = (const float*)d_in[4];
    const float* Wq = (const float*)d_in[5];
    const float* bq = (const float*)d_in[6];
    const float* Wk = (const float*)d_in[7];
    const float* bk = (const float*)d_in[8];
    const float* Wv = (const float*)d_in[9];
    const float* bv = (const float*)d_in[10];
    const float* Wo = (const float*)d_in[11];
    const float* bo = (const float*)d_in[12];
    float* out = (float*)d_out;

    float *gq, *gk, *gv, *gao;
    cudaGetSymbolAddress((void**)&gq,  g_Q);
    cudaGetSymbolAddress((void**)&gk,  g_K);
    cudaGetSymbolAddress((void**)&gv,  g_V);
    cudaGetSymbolAddress((void**)&gao, g_AO);

    cudaFuncSetAttribute(attn_kernel,
                         cudaFuncAttributeMaxDynamicSharedMemorySize,
                         ATT_SMEM_BYTES);

    dim3 gblk(256);
    dim3 ggrid(H_ / 128, M_ / 128);   // (8, 32)
    gemm_mma_kernel<<<ggrid, gblk>>>(query, Wq, bq, gq);
    gemm_mma_kernel<<<ggrid, gblk>>>(key,   Wk, bk, gk);
    gemm_mma_kernel<<<ggrid, gblk>>>(value, Wv, bv, gv);

    dim3 agrid(S_ / 128, NH_, B_);    // (16, 16, 2)
    attn_kernel<<<agrid, 256, ATT_SMEM_BYTES>>>(gq, gk, gv, mask, smask, gao);

    gemm_mma_kernel<<<ggrid, gblk>>>(gao, Wo, bo, out);
}

// round 4
// speedup vs baseline: 2.5568x; 1.8548x over previous
#include <cuda_runtime.h>
#include <cstdint>
#include <cstddef>

#define B_  2
#define S_  2048
#define H_  1024
#define NH_ 16
#define HD_ 64
#define M_  (B_ * S_)   // 4096 rows

// Scratch (allocation-free rule: __device__ globals)
__device__ float g_Q[(size_t)M_ * H_];
__device__ float g_K[(size_t)M_ * H_];
__device__ float g_V[(size_t)M_ * H_];
__device__ float g_AO[(size_t)M_ * H_];
__device__ float g_FM[(size_t)B_ * S_ * S_];   // fused mask: -1 or sm*0.125

// ---------------------------------------------------------------------------
__device__ __forceinline__ uint32_t f32_to_tf32(float x) {
    uint32_t u;
    asm("cvt.rna.tf32.f32 %0, %1;" : "=r"(u) : "f"(x));
    return u;
}
__device__ __forceinline__ float round_tf32(float x) {
    return __uint_as_float(f32_to_tf32(x));
}

__device__ __forceinline__ void mma_tf32(float& d0, float& d1, float& d2, float& d3,
                                         uint32_t a0, uint32_t a1, uint32_t a2, uint32_t a3,
                                         uint32_t b0, uint32_t b1) {
    asm volatile(
        "mma.sync.aligned.m16n8k8.row.col.f32.tf32.tf32.f32 "
        "{%0,%1,%2,%3}, {%4,%5,%6,%7}, {%8,%9}, {%0,%1,%2,%3};"
        : "+f"(d0), "+f"(d1), "+f"(d2), "+f"(d3)
        : "r"(a0), "r"(a1), "r"(a2), "r"(a3), "r"(b0), "r"(b1));
}

__device__ __forceinline__ uint32_t smem_u32(const void* p) {
    uint32_t a;
    asm("{ .reg .u64 t; cvta.to.shared.u64 t, %1; cvt.u32.u64 %0, t; }"
        : "=r"(a) : "l"(p));
    return a;
}
__device__ __forceinline__ void cp_async16(uint32_t dst, const void* src) {
    asm volatile("cp.async.ca.shared.global [%0], [%1], 16;"
                 :: "r"(dst), "l"(src) : "memory");
}
__device__ __forceinline__ void cp_commit() {
    asm volatile("cp.async.commit_group;" ::: "memory");
}

// ===========================================================================
// Fused mask: fm = (mask==0) ? -1 : script_mask * 0.125   (script_mask >= 0)
// ===========================================================================
__global__ __launch_bounds__(256)
void fuse_mask_kernel(const int* __restrict__ mask, const float* __restrict__ sm,
                      float* __restrict__ fm)
{
    int i = blockIdx.x * 256 + threadIdx.x;
    const int4*   m4 = (const int4*)mask;
    const float4* s4 = (const float4*)sm;
    float4*       f4 = (float4*)fm;
    int4   m = m4[i];
    float4 s = s4[i];
    float4 o;
    o.x = (m.x == 0) ? -1.0f : s.x * 0.125f;
    o.y = (m.y == 0) ? -1.0f : s.y * 0.125f;
    o.z = (m.z == 0) ? -1.0f : s.z * 0.125f;
    o.w = (m.w == 0) ? -1.0f : s.w * 0.125f;
    f4[i] = o;
}

// ===========================================================================
// tf32 mma.sync GEMM (from R3), templated on output rounding to tf32
// ===========================================================================
#define PAD_ 20

template <bool ROUND_OUT>
__global__ __launch_bounds__(256, 2)
void gemm_mma_kernel(const float* __restrict__ X, const float* __restrict__ W,
                     const float* __restrict__ bias, float* __restrict__ C)
{
    __shared__ float As[128 * PAD_];
    __shared__ float Bs[128 * PAD_];

    const int tid  = threadIdx.x;
    const int wid  = tid >> 5;
    const int lane = tid & 31;
    const int m0   = blockIdx.y * 128;
    const int n0   = blockIdx.x * 128;
    const int warp_m = (wid & 1) * 64;
    const int warp_n = (wid >> 1) * 32;
    const int qrow = lane >> 2;
    const int qcol = lane & 3;

    const int r0 = tid >> 2;
    const int c0 = (tid & 3) * 4;
    const int r1 = (tid + 256) >> 2;
    const int c1 = ((tid + 256) & 3) * 4;

    const float* Xa0 = X + (size_t)(m0 + r0) * H_ + c0;
    const float* Xa1 = X + (size_t)(m0 + r1) * H_ + c1;
    const float* Wb0 = W + (size_t)(n0 + r0) * H_ + c0;
    const float* Wb1 = W + (size_t)(n0 + r1) * H_ + c1;

    float acc[16][4];
#pragma unroll
    for (int i = 0; i < 16; ++i)
#pragma unroll
        for (int j = 0; j < 4; ++j) acc[i][j] = 0.0f;

    float4 ra0 = *(const float4*)Xa0;
    float4 ra1 = *(const float4*)Xa1;
    float4 rb0 = *(const float4*)Wb0;
    float4 rb1 = *(const float4*)Wb1;

    const int NCHUNK = H_ / 16;

    for (int c = 0; c < NCHUNK; ++c) {
        if (c > 0) __syncthreads();
        {
            uint4 ua0 = make_uint4(f32_to_tf32(ra0.x), f32_to_tf32(ra0.y),
                                   f32_to_tf32(ra0.z), f32_to_tf32(ra0.w));
            uint4 ua1 = make_uint4(f32_to_tf32(ra1.x), f32_to_tf32(ra1.y),
                                   f32_to_tf32(ra1.z), f32_to_tf32(ra1.w));
            uint4 ub0 = make_uint4(f32_to_tf32(rb0.x), f32_to_tf32(rb0.y),
                                   f32_to_tf32(rb0.z), f32_to_tf32(rb0.w));
            uint4 ub1 = make_uint4(f32_to_tf32(rb1.x), f32_to_tf32(rb1.y),
                                   f32_to_tf32(rb1.z), f32_to_tf32(rb1.w));
            *(uint4*)&As[r0 * PAD_ + c0] = ua0;
            *(uint4*)&As[r1 * PAD_ + c1] = ua1;
            *(uint4*)&Bs[r0 * PAD_ + c0] = ub0;
            *(uint4*)&Bs[r1 * PAD_ + c1] = ub1;
        }
        __syncthreads();

        if (c + 1 < NCHUNK) {
            int k0 = (c + 1) * 16;
            ra0 = *(const float4*)(Xa0 + k0);
            ra1 = *(const float4*)(Xa1 + k0);
            rb0 = *(const float4*)(Wb0 + k0);
            rb1 = *(const float4*)(Wb1 + k0);
        }

#pragma unroll
        for (int ks = 0; ks < 2; ++ks) {
            const int kk = ks * 8;
            uint32_t af[4][4];
            uint32_t bf[4][2];
#pragma unroll
            for (int mt = 0; mt < 4; ++mt) {
                const float* ap = &As[(warp_m + mt * 16 + qrow) * PAD_ + kk + qcol];
                af[mt][0] = __float_as_uint(ap[0]);
                af[mt][1] = __float_as_uint(ap[8 * PAD_]);
                af[mt][2] = __float_as_uint(ap[4]);
                af[mt][3] = __float_as_uint(ap[8 * PAD_ + 4]);
            }
#pragma unroll
            for (int nt = 0; nt < 4; ++nt) {
                const float* bp = &Bs[(warp_n + nt * 8 + qrow) * PAD_ + kk + qcol];
                bf[nt][0] = __float_as_uint(bp[0]);
                bf[nt][1] = __float_as_uint(bp[4]);
            }
#pragma unroll
            for (int mt = 0; mt < 4; ++mt)
#pragma unroll
                for (int nt = 0; nt < 4; ++nt)
                    mma_tf32(acc[mt * 4 + nt][0], acc[mt * 4 + nt][1],
                             acc[mt * 4 + nt][2], acc[mt * 4 + nt][3],
                             af[mt][0], af[mt][1], af[mt][2], af[mt][3],
                             bf[nt][0], bf[nt][1]);
        }
    }

#pragma unroll
    for (int mt = 0; mt < 4; ++mt) {
        int row = m0 + warp_m + mt * 16 + qrow;
#pragma unroll
        for (int nt = 0; nt < 4; ++nt) {
            int col = n0 + warp_n + nt * 8 + 2 * qcol;
            float b0v = bias[col];
            float b1v = bias[col + 1];
            float v00 = acc[mt * 4 + nt][0] + b0v;
            float v01 = acc[mt * 4 + nt][1] + b1v;
            float v10 = acc[mt * 4 + nt][2] + b0v;
            float v11 = acc[mt * 4 + nt][3] + b1v;
            if (ROUND_OUT) {
                v00 = round_tf32(v00); v01 = round_tf32(v01);
                v10 = round_tf32(v10); v11 = round_tf32(v11);
            }
            float* cp0 = C + (size_t)row * H_ + col;
            float* cp1 = C + (size_t)(row + 8) * H_ + col;
            *(float2*)cp0 = make_float2(v00, v01);
            *(float2*)cp1 = make_float2(v10, v11);
        }
    }
}

// ===========================================================================
// tf32 mma.sync flash attention
// CTA: 128 Q rows, 8 warps x 16 rows. KV chunk 128, 2-stage cp.async pipeline.
// S-fragment reused as PV A-fragment via register permute + V-row permute.
// ===========================================================================
#define KVC 128
#define NCH (S_ / KVC)          // 16
#define VST 68                  // smem row stride (floats)
#define STG_FLOATS (2 * KVC * VST)        // K tile + V tile, one stage
#define ATT_SMEM_BYTES (2 * STG_FLOATS * 4)   // 2 stages = 139264 B

__global__ __launch_bounds__(256, 1)
void attn_mma_kernel(const float* __restrict__ Qg, const float* __restrict__ Kg,
                     const float* __restrict__ Vg, const float* __restrict__ FM,
                     float* __restrict__ Og)
{
    extern __shared__ float smem[];
    const uint32_t sb = smem_u32(smem);

    const int tid  = threadIdx.x;
    const int wid  = tid >> 5;
    const int lane = tid & 31;
    const int gr   = lane >> 2;    // 0..7
    const int qc   = lane & 3;     // 0..3
    const int q0   = blockIdx.x * 128;
    const int h    = blockIdx.y;
    const int b    = blockIdx.z;
    const int wrow = wid * 16;

    const size_t base = (size_t)b * S_ * H_ + (size_t)h * HD_;

    // Q fragments (g_Q already tf32-rounded): a0(gr,c) a1(gr+8,c) a2(gr,c+4) a3(gr+8,c+4)
    uint32_t qf[8][4];
    {
        const float* Qr0 = Qg + base + (size_t)(q0 + wrow + gr) * H_;
        const float* Qr1 = Qg + base + (size_t)(q0 + wrow + gr + 8) * H_;
#pragma unroll
        for (int ks = 0; ks < 8; ++ks) {
            int c = ks * 8 + qc;
            qf[ks][0] = __float_as_uint(__ldg(Qr0 + c));
            qf[ks][1] = __float_as_uint(__ldg(Qr1 + c));
            qf[ks][2] = __float_as_uint(__ldg(Qr0 + c + 4));
            qf[ks][3] = __float_as_uint(__ldg(Qr1 + c + 4));
        }
    }

    float oacc[8][4];
#pragma unroll
    for (int i = 0; i < 8; ++i)
#pragma unroll
        for (int j = 0; j < 4; ++j) oacc[i][j] = 0.0f;
    float m_lo = -1e30f, m_hi = -1e30f, l_lo = 0.0f, l_hi = 0.0f;

    // K/V tile prefetch (cp.async): thread i -> row i>>4, 16B col block i&15
    const int prow = tid >> 4;          // + {0,64} over 8 iters... use loop
    const int pcc  = tid & 15;

    auto issue_chunk = [&](int c) {
        const int st = c & 1;
        const uint32_t kbase = sb + (uint32_t)(st * STG_FLOATS) * 4;
        const uint32_t vbase = kbase + (uint32_t)(KVC * VST) * 4;
        const int k0 = c * KVC;
#pragma unroll
        for (int it = 0; it < 8; ++it) {
            int row = prow + it * 16;
            const float* ksrc = Kg + base + (size_t)(k0 + row) * H_ + pcc * 4;
            const float* vsrc = Vg + base + (size_t)(k0 + row) * H_ + pcc * 4;
            uint32_t doff = (uint32_t)(row * VST) * 4 + pcc * 16;
            cp_async16(kbase + doff, ksrc);
            cp_async16(vbase + doff, vsrc);
        }
        cp_commit();
    };

    issue_chunk(0);

    const size_t fmbase_lo = ((size_t)b * S_ + (q0 + wrow + gr)) * S_;
    const size_t fmbase_hi = fmbase_lo + (size_t)8 * S_;

    for (int c = 0; c < NCH; ++c) {
        if (c > 0) __syncthreads();           // all warps done reading stage (c+1)&1
        if (c + 1 < NCH) issue_chunk(c + 1);
        if (c + 1 < NCH) asm volatile("cp.async.wait_group 1;" ::: "memory");
        else             asm volatile("cp.async.wait_group 0;" ::: "memory");
        __syncthreads();                      // stage c&1 ready

        const int st = c & 1;
        const float* Ks = smem + st * STG_FLOATS;
        const float* Vs = Ks + KVC * VST;
        const int k0 = c * KVC;

        // ---- S = Q K^T : sv[nt][4], nt = KV col block ----
        float sv[16][4];
#pragma unroll
        for (int i = 0; i < 16; ++i)
#pragma unroll
            for (int j = 0; j < 4; ++j) sv[i][j] = 0.0f;

#pragma unroll
        for (int ks = 0; ks < 8; ++ks) {
            const int kk = ks * 8 + qc;
#pragma unroll
            for (int nt = 0; nt < 16; ++nt) {
                const float* bp = &Ks[(nt * 8 + gr) * VST + kk];
                uint32_t b0 = __float_as_uint(bp[0]);
                uint32_t b1 = __float_as_uint(bp[4]);
                mma_tf32(sv[nt][0], sv[nt][1], sv[nt][2], sv[nt][3],
                         qf[ks][0], qf[ks][1], qf[ks][2], qf[ks][3], b0, b1);
            }
        }

        // ---- fused mask + row max ----
        float tmax_lo = -1e30f, tmax_hi = -1e30f;
#pragma unroll
        for (int nt = 0; nt < 16; ++nt) {
            int colo = k0 + nt * 8 + 2 * qc;
            float2 fl = *(const float2*)&FM[fmbase_lo + colo];
            float2 fh = *(const float2*)&FM[fmbase_hi + colo];
            float s0 = (fl.x < 0.0f) ? -1e30f : sv[nt][0] * fl.x;
            float s1 = (fl.y < 0.0f) ? -1e30f : sv[nt][1] * fl.y;
            float s2 = (fh.x < 0.0f) ? -1e30f : sv[nt][2] * fh.x;
            float s3 = (fh.y < 0.0f) ? -1e30f : sv[nt][3] * fh.y;
            sv[nt][0] = s0; sv[nt][1] = s1; sv[nt][2] = s2; sv[nt][3] = s3;
            tmax_lo = fmaxf(tmax_lo, fmaxf(s0, s1));
            tmax_hi = fmaxf(tmax_hi, fmaxf(s2, s3));
        }
        tmax_lo = fmaxf(tmax_lo, __shfl_xor_sync(0xffffffffu, tmax_lo, 1));
        tmax_lo = fmaxf(tmax_lo, __shfl_xor_sync(0xffffffffu, tmax_lo, 2));
        tmax_hi = fmaxf(tmax_hi, __shfl_xor_sync(0xffffffffu, tmax_hi, 1));
        tmax_hi = fmaxf(tmax_hi, __shfl_xor_sync(0xffffffffu, tmax_hi, 2));

        float newm_lo = fmaxf(m_lo, tmax_lo);
        float newm_hi = fmaxf(m_hi, tmax_hi);
        float alpha_lo = __expf(m_lo - newm_lo);
        float alpha_hi = __expf(m_hi - newm_hi);
        m_lo = newm_lo; m_hi = newm_hi;

        // ---- exp + row sum (P replaces S in sv) ----
        float rs_lo = 0.0f, rs_hi = 0.0f;
#pragma unroll
        for (int nt = 0; nt < 16; ++nt) {
            float p0 = __expf(sv[nt][0] - newm_lo);
            float p1 = __expf(sv[nt][1] - newm_lo);
            float p2 = __expf(sv[nt][2] - newm_hi);
            float p3 = __expf(sv[nt][3] - newm_hi);
            rs_lo += p0 + p1;
            rs_hi += p2 + p3;
            sv[nt][0] = p0; sv[nt][1] = p1; sv[nt][2] = p2; sv[nt][3] = p3;
        }
        rs_lo += __shfl_xor_sync(0xffffffffu, rs_lo, 1);
        rs_lo += __shfl_xor_sync(0xffffffffu, rs_lo, 2);
        rs_hi += __shfl_xor_sync(0xffffffffu, rs_hi, 1);
        rs_hi += __shfl_xor_sync(0xffffffffu, rs_hi, 2);
        l_lo = l_lo * alpha_lo + rs_lo;
        l_hi = l_hi * alpha_hi + rs_hi;

        // ---- rescale O ----
#pragma unroll
        for (int nt = 0; nt < 8; ++nt) {
            oacc[nt][0] *= alpha_lo; oacc[nt][1] *= alpha_lo;
            oacc[nt][2] *= alpha_hi; oacc[nt][3] *= alpha_hi;
        }

        // ---- O += P V : P fragment = S C-frag permuted (c0,c2,c1,c3);
        //      V rows permuted: mma-k j<4 -> real row 2j, j>=4 -> 2(j-4)+1 ----
#pragma unroll
        for (int ks = 0; ks < 16; ++ks) {
            uint32_t a0 = f32_to_tf32(sv[ks][0]);
            uint32_t a1 = f32_to_tf32(sv[ks][2]);
            uint32_t a2 = f32_to_tf32(sv[ks][1]);
            uint32_t a3 = f32_to_tf32(sv[ks][3]);
            const int vr0 = ks * 8 + 2 * qc;
#pragma unroll
            for (int nt = 0; nt < 8; ++nt) {
                uint32_t b0 = __float_as_uint(Vs[vr0 * VST + nt * 8 + gr]);
                uint32_t b1 = __float_as_uint(Vs[(vr0 + 1) * VST + nt * 8 + gr]);
                mma_tf32(oacc[nt][0], oacc[nt][1], oacc[nt][2], oacc[nt][3],
                         a0, a1, a2, a3, b0, b1);
            }
        }
    }

    // ---- epilogue ----
    float inv_lo = 1.0f / l_lo;
    float inv_hi = 1.0f / l_hi;
    float* Or0 = Og + base + (size_t)(q0 + wrow + gr) * H_;
    float* Or1 = Og + base + (size_t)(q0 + wrow + gr + 8) * H_;
#pragma unroll
    for (int nt = 0; nt < 8; ++nt) {
        int col = nt * 8 + 2 * qc;
        *(float2*)(Or0 + col) = make_float2(oacc[nt][0] * inv_lo, oacc[nt][1] * inv_lo);
        *(float2*)(Or1 + col) = make_float2(oacc[nt][2] * inv_hi, oacc[nt][3] * inv_hi);
    }
}

// ---------------------------------------------------------------------------
extern "C" void kernel_launch(void* const* d_in, const int* in_sizes, int n_in,
                              void* d_out, int out_size)
{
    const float* query = (const float*)d_in[0];
    const float* key   = (const float*)d_in[1];
    const float* value = (const float*)d_in[2];
    const int*   mask  = (const int*)d_in[3];
    const float* smask = (const float*)d_in[4];
    const float* Wq = (const float*)d_in[5];
    const float* bq = (const float*)d_in[6];
    const float* Wk = (const float*)d_in[7];
    const float* bk = (const float*)d_in[8];
    const float* Wv = (const float*)d_in[9];
    const float* bv = (const float*)d_in[10];
    const float* Wo = (const float*)d_in[11];
    const float* bo = (const float*)d_in[12];
    float* out = (float*)d_out;

    float *gq, *gk, *gv, *gao, *gfm;
    cudaGetSymbolAddress((void**)&gq,  g_Q);
    cudaGetSymbolAddress((void**)&gk,  g_K);
    cudaGetSymbolAddress((void**)&gv,  g_V);
    cudaGetSymbolAddress((void**)&gao, g_AO);
    cudaGetSymbolAddress((void**)&gfm, g_FM);

    cudaFuncSetAttribute(attn_mma_kernel,
                         cudaFuncAttributeMaxDynamicSharedMemorySize,
                         ATT_SMEM_BYTES);

    // fused mask
    fuse_mask_kernel<<<(B_ * S_ * S_ / 4) / 256, 256>>>(mask, smask, gfm);

    dim3 gblk(256);
    dim3 ggrid(H_ / 128, M_ / 128);   // (8, 32)
    gemm_mma_kernel<true ><<<ggrid, gblk>>>(query, Wq, bq, gq);
    gemm_mma_kernel<true ><<<ggrid, gblk>>>(key,   Wk, bk, gk);
    gemm_mma_kernel<true ><<<ggrid, gblk>>>(value, Wv, bv, gv);

    dim3 agrid(S_ / 128, NH_, B_);    // (16, 16, 2)
    attn_mma_kernel<<<agrid, 256, ATT_SMEM_BYTES>>>(gq, gk, gv, gfm, gao);

    gemm_mma_kernel<false><<<ggrid, gblk>>>(gao, Wo, bo, out);
}

// round 5
// speedup vs baseline: 2.8191x; 1.1026x over previous
#include <cuda_runtime.h>
#include <cstdint>
#include <cstddef>

#define B_  2
#define S_  2048
#define H_  1024
#define NH_ 16
#define HD_ 64
#define M_  (B_ * S_)   // 4096 rows

// Scratch (allocation-free rule: __device__ globals)
__device__ float g_Q[(size_t)M_ * H_];
__device__ float g_K[(size_t)M_ * H_];
__device__ float g_V[(size_t)M_ * H_];
__device__ float g_AO[(size_t)M_ * H_];
__device__ float g_FM[(size_t)B_ * S_ * S_];   // fused mask: -1 or sm*0.125

// ---------------------------------------------------------------------------
__device__ __forceinline__ uint32_t f32_to_tf32(float x) {
    uint32_t u;
    asm("cvt.rna.tf32.f32 %0, %1;" : "=r"(u) : "f"(x));
    return u;
}
__device__ __forceinline__ float round_tf32(float x) {
    return __uint_as_float(f32_to_tf32(x));
}

__device__ __forceinline__ void mma_tf32(float& d0, float& d1, float& d2, float& d3,
                                         uint32_t a0, uint32_t a1, uint32_t a2, uint32_t a3,
                                         uint32_t b0, uint32_t b1) {
    asm volatile(
        "mma.sync.aligned.m16n8k8.row.col.f32.tf32.tf32.f32 "
        "{%0,%1,%2,%3}, {%4,%5,%6,%7}, {%8,%9}, {%0,%1,%2,%3};"
        : "+f"(d0), "+f"(d1), "+f"(d2), "+f"(d3)
        : "r"(a0), "r"(a1), "r"(a2), "r"(a3), "r"(b0), "r"(b1));
}

__device__ __forceinline__ uint32_t smem_u32(const void* p) {
    uint32_t a;
    asm("{ .reg .u64 t; cvta.to.shared.u64 t, %1; cvt.u32.u64 %0, t; }"
        : "=r"(a) : "l"(p));
    return a;
}
__device__ __forceinline__ void cp_async16(uint32_t dst, const void* src) {
    asm volatile("cp.async.ca.shared.global [%0], [%1], 16;"
                 :: "r"(dst), "l"(src) : "memory");
}
__device__ __forceinline__ void cp_commit() {
    asm volatile("cp.async.commit_group;" ::: "memory");
}
template <int N>
__device__ __forceinline__ void cp_wait() {
    asm volatile("cp.async.wait_group %0;" :: "n"(N) : "memory");
}

// ===========================================================================
// Fused mask: fm = (mask==0) ? -1 : script_mask * 0.125   (script_mask >= 0)
// ===========================================================================
__global__ __launch_bounds__(256)
void fuse_mask_kernel(const int* __restrict__ mask, const float* __restrict__ sm,
                      float* __restrict__ fm)
{
    int i = blockIdx.x * 256 + threadIdx.x;
    int4   m = ((const int4*)mask)[i];
    float4 s = ((const float4*)sm)[i];
    float4 o;
    o.x = (m.x == 0) ? -1.0f : s.x * 0.125f;
    o.y = (m.y == 0) ? -1.0f : s.y * 0.125f;
    o.z = (m.z == 0) ? -1.0f : s.z * 0.125f;
    o.w = (m.w == 0) ? -1.0f : s.w * 0.125f;
    ((float4*)fm)[i] = o;
}

// ===========================================================================
// tf32 mma.sync GEMM body: C = X @ W^T + bias. CTA 128x128, warp 64x32.
// 3-stage cp.async pipeline, K chunk 16, tf32 cvt at fragment load time.
// ===========================================================================
#define PAD_ 20
#define G_STAGE_FLOATS (2 * 128 * PAD_)            // A + B, one stage
#define G_SMEM_BYTES   (3 * G_STAGE_FLOATS * 4)    // 61440

__device__ __forceinline__ void gemm_body(
    const float* __restrict__ X, const float* __restrict__ W,
    const float* __restrict__ bias, float* __restrict__ C, bool round_out)
{
    extern __shared__ float gsm[];
    const uint32_t sb = smem_u32(gsm);

    const int tid  = threadIdx.x;
    const int wid  = tid >> 5;
    const int lane = tid & 31;
    const int m0   = blockIdx.y * 128;
    const int n0   = blockIdx.x * 128;
    const int warp_m = (wid & 1) * 64;
    const int warp_n = (wid >> 1) * 32;
    const int qrow = lane >> 2;
    const int qcol = lane & 3;

    const int r0 = tid >> 2;             // 0..63
    const int c0 = (tid & 3) * 4;        // 0,4,8,12

    const float* Xa0 = X + (size_t)(m0 + r0) * H_ + c0;
    const float* Xa1 = X + (size_t)(m0 + r0 + 64) * H_ + c0;
    const float* Wb0 = W + (size_t)(n0 + r0) * H_ + c0;
    const float* Wb1 = W + (size_t)(n0 + r0 + 64) * H_ + c0;

    const uint32_t da0 = sb + (uint32_t)(r0 * PAD_ + c0) * 4;
    const uint32_t da1 = sb + (uint32_t)((r0 + 64) * PAD_ + c0) * 4;
    const uint32_t db0 = da0 + (uint32_t)(128 * PAD_) * 4;
    const uint32_t db1 = da1 + (uint32_t)(128 * PAD_) * 4;

    const int NCHUNK = H_ / 16;  // 64

    auto issue = [&](int c) {
        const uint32_t so = (uint32_t)((c % 3) * G_STAGE_FLOATS) * 4;
        const int k0 = c * 16;
        cp_async16(da0 + so, Xa0 + k0);
        cp_async16(da1 + so, Xa1 + k0);
        cp_async16(db0 + so, Wb0 + k0);
        cp_async16(db1 + so, Wb1 + k0);
        cp_commit();
    };

    float acc[16][4];
#pragma unroll
    for (int i = 0; i < 16; ++i)
#pragma unroll
        for (int j = 0; j < 4; ++j) acc[i][j] = 0.0f;

    issue(0);
    issue(1);

    for (int c = 0; c < NCHUNK; ++c) {
        cp_wait<1>();
        __syncthreads();
        if (c + 2 < NCHUNK) issue(c + 2);

        const float* As = gsm + (c % 3) * G_STAGE_FLOATS;
        const float* Bs = As + 128 * PAD_;

#pragma unroll
        for (int ks = 0; ks < 2; ++ks) {
            const int kk = ks * 8;
            uint32_t af[4][4];
            uint32_t bf[4][2];
#pragma unroll
            for (int mt = 0; mt < 4; ++mt) {
                const float* ap = &As[(warp_m + mt * 16 + qrow) * PAD_ + kk + qcol];
                af[mt][0] = f32_to_tf32(ap[0]);
                af[mt][1] = f32_to_tf32(ap[8 * PAD_]);
                af[mt][2] = f32_to_tf32(ap[4]);
                af[mt][3] = f32_to_tf32(ap[8 * PAD_ + 4]);
            }
#pragma unroll
            for (int nt = 0; nt < 4; ++nt) {
                const float* bp = &Bs[(warp_n + nt * 8 + qrow) * PAD_ + kk + qcol];
                bf[nt][0] = f32_to_tf32(bp[0]);
                bf[nt][1] = f32_to_tf32(bp[4]);
            }
#pragma unroll
            for (int mt = 0; mt < 4; ++mt)
#pragma unroll
                for (int nt = 0; nt < 4; ++nt)
                    mma_tf32(acc[mt * 4 + nt][0], acc[mt * 4 + nt][1],
                             acc[mt * 4 + nt][2], acc[mt * 4 + nt][3],
                             af[mt][0], af[mt][1], af[mt][2], af[mt][3],
                             bf[nt][0], bf[nt][1]);
        }
        __syncthreads();
    }

#pragma unroll
    for (int mt = 0; mt < 4; ++mt) {
        int row = m0 + warp_m + mt * 16 + qrow;
#pragma unroll
        for (int nt = 0; nt < 4; ++nt) {
            int col = n0 + warp_n + nt * 8 + 2 * qcol;
            float b0v = bias[col];
            float b1v = bias[col + 1];
            float v00 = acc[mt * 4 + nt][0] + b0v;
            float v01 = acc[mt * 4 + nt][1] + b1v;
            float v10 = acc[mt * 4 + nt][2] + b0v;
            float v11 = acc[mt * 4 + nt][3] + b1v;
            if (round_out) {
                v00 = round_tf32(v00); v01 = round_tf32(v01);
                v10 = round_tf32(v10); v11 = round_tf32(v11);
            }
            *(float2*)(C + (size_t)row * H_ + col)       = make_float2(v00, v01);
            *(float2*)(C + (size_t)(row + 8) * H_ + col) = make_float2(v10, v11);
        }
    }
}

// Fused Q/K/V projections: blockIdx.z selects input/weight/output triple
__global__ __launch_bounds__(256, 2)
void qkv_gemm_kernel(const float* __restrict__ q_in, const float* __restrict__ k_in,
                     const float* __restrict__ v_in,
                     const float* __restrict__ Wq, const float* __restrict__ Wk,
                     const float* __restrict__ Wv,
                     const float* __restrict__ bq, const float* __restrict__ bk,
                     const float* __restrict__ bv,
                     float* __restrict__ Cq, float* __restrict__ Ck,
                     float* __restrict__ Cv)
{
    const int z = blockIdx.z;
    const float* X = (z == 0) ? q_in : (z == 1) ? k_in : v_in;
    const float* W = (z == 0) ? Wq   : (z == 1) ? Wk   : Wv;
    const float* bias = (z == 0) ? bq : (z == 1) ? bk  : bv;
    float* C = (z == 0) ? Cq : (z == 1) ? Ck : Cv;
    gemm_body(X, W, bias, C, true);
}

__global__ __launch_bounds__(256, 2)
void out_gemm_kernel(const float* __restrict__ X, const float* __restrict__ W,
                     const float* __restrict__ bias, float* __restrict__ C)
{
    gemm_body(X, W, bias, C, false);
}

// ===========================================================================
// tf32 mma.sync flash attention
// CTA: 128 Q rows, 8 warps x 16 rows. KV chunk 64, 2-stage cp.async, occ 2.
// S-fragment reused as PV A-fragment via register permute + V-row permute.
// ===========================================================================
#define KVC 64
#define NCH (S_ / KVC)          // 32
#define VST 68                  // smem row stride (floats)
#define STG_FLOATS (2 * KVC * VST)            // K tile + V tile, one stage
#define ATT_SMEM_BYTES (2 * STG_FLOATS * 4)   // 2 stages = 69632 B

__global__ __launch_bounds__(256, 2)
void attn_mma_kernel(const float* __restrict__ Qg, const float* __restrict__ Kg,
                     const float* __restrict__ Vg, const float* __restrict__ FM,
                     float* __restrict__ Og)
{
    extern __shared__ float smem[];
    const uint32_t sb = smem_u32(smem);

    const int tid  = threadIdx.x;
    const int wid  = tid >> 5;
    const int lane = tid & 31;
    const int gr   = lane >> 2;    // 0..7
    const int qc   = lane & 3;     // 0..3
    const int q0   = blockIdx.x * 128;
    const int h    = blockIdx.y;
    const int b    = blockIdx.z;
    const int wrow = wid * 16;

    const size_t base = (size_t)b * S_ * H_ + (size_t)h * HD_;

    // Q fragments (g_Q already tf32-rounded)
    uint32_t qf[8][4];
    {
        const float* Qr0 = Qg + base + (size_t)(q0 + wrow + gr) * H_;
        const float* Qr1 = Qg + base + (size_t)(q0 + wrow + gr + 8) * H_;
#pragma unroll
        for (int ks = 0; ks < 8; ++ks) {
            int c = ks * 8 + qc;
            qf[ks][0] = __float_as_uint(__ldg(Qr0 + c));
            qf[ks][1] = __float_as_uint(__ldg(Qr1 + c));
            qf[ks][2] = __float_as_uint(__ldg(Qr0 + c + 4));
            qf[ks][3] = __float_as_uint(__ldg(Qr1 + c + 4));
        }
    }

    float oacc[8][4];
#pragma unroll
    for (int i = 0; i < 8; ++i)
#pragma unroll
        for (int j = 0; j < 4; ++j) oacc[i][j] = 0.0f;
    float m_lo = -1e30f, m_hi = -1e30f, l_lo = 0.0f, l_hi = 0.0f;

    const int prow = tid >> 4;          // 0..15
    const int pcc  = tid & 15;

    auto issue_chunk = [&](int c) {
        const int st = c & 1;
        const uint32_t kbase = sb + (uint32_t)(st * STG_FLOATS) * 4;
        const uint32_t vbase = kbase + (uint32_t)(KVC * VST) * 4;
        const int k0 = c * KVC;
#pragma unroll
        for (int it = 0; it < 4; ++it) {
            int row = prow + it * 16;
            const float* ksrc = Kg + base + (size_t)(k0 + row) * H_ + pcc * 4;
            const float* vsrc = Vg + base + (size_t)(k0 + row) * H_ + pcc * 4;
            uint32_t doff = (uint32_t)(row * VST) * 4 + pcc * 16;
            cp_async16(kbase + doff, ksrc);
            cp_async16(vbase + doff, vsrc);
        }
        cp_commit();
    };

    issue_chunk(0);

    const size_t fmbase_lo = ((size_t)b * S_ + (q0 + wrow + gr)) * S_;
    const size_t fmbase_hi = fmbase_lo + (size_t)8 * S_;

    for (int c = 0; c < NCH; ++c) {
        if (c > 0) __syncthreads();
        if (c + 1 < NCH) { issue_chunk(c + 1); cp_wait<1>(); }
        else             { cp_wait<0>(); }
        __syncthreads();

        const int st = c & 1;
        const float* Ks = smem + st * STG_FLOATS;
        const float* Vs = Ks + KVC * VST;
        const int k0 = c * KVC;

        // ---- S = Q K^T ----
        float sv[8][4];
#pragma unroll
        for (int i = 0; i < 8; ++i)
#pragma unroll
            for (int j = 0; j < 4; ++j) sv[i][j] = 0.0f;

#pragma unroll
        for (int ks = 0; ks < 8; ++ks) {
            const int kk = ks * 8 + qc;
#pragma unroll
            for (int nt = 0; nt < 8; ++nt) {
                const float* bp = &Ks[(nt * 8 + gr) * VST + kk];
                uint32_t b0 = __float_as_uint(bp[0]);
                uint32_t b1 = __float_as_uint(bp[4]);
                mma_tf32(sv[nt][0], sv[nt][1], sv[nt][2], sv[nt][3],
                         qf[ks][0], qf[ks][1], qf[ks][2], qf[ks][3], b0, b1);
            }
        }

        // ---- fused mask + row max ----
        float tmax_lo = -1e30f, tmax_hi = -1e30f;
#pragma unroll
        for (int nt = 0; nt < 8; ++nt) {
            int colo = k0 + nt * 8 + 2 * qc;
            float2 fl = *(const float2*)&FM[fmbase_lo + colo];
            float2 fh = *(const float2*)&FM[fmbase_hi + colo];
            float s0 = (fl.x < 0.0f) ? -1e30f : sv[nt][0] * fl.x;
            float s1 = (fl.y < 0.0f) ? -1e30f : sv[nt][1] * fl.y;
            float s2 = (fh.x < 0.0f) ? -1e30f : sv[nt][2] * fh.x;
            float s3 = (fh.y < 0.0f) ? -1e30f : sv[nt][3] * fh.y;
            sv[nt][0] = s0; sv[nt][1] = s1; sv[nt][2] = s2; sv[nt][3] = s3;
            tmax_lo = fmaxf(tmax_lo, fmaxf(s0, s1));
            tmax_hi = fmaxf(tmax_hi, fmaxf(s2, s3));
        }
        tmax_lo = fmaxf(tmax_lo, __shfl_xor_sync(0xffffffffu, tmax_lo, 1));
        tmax_lo = fmaxf(tmax_lo, __shfl_xor_sync(0xffffffffu, tmax_lo, 2));
        tmax_hi = fmaxf(tmax_hi, __shfl_xor_sync(0xffffffffu, tmax_hi, 1));
        tmax_hi = fmaxf(tmax_hi, __shfl_xor_sync(0xffffffffu, tmax_hi, 2));

        float newm_lo = fmaxf(m_lo, tmax_lo);
        float newm_hi = fmaxf(m_hi, tmax_hi);
        float alpha_lo = __expf(m_lo - newm_lo);
        float alpha_hi = __expf(m_hi - newm_hi);
        m_lo = newm_lo; m_hi = newm_hi;

        // ---- exp + row sum ----
        float rs_lo = 0.0f, rs_hi = 0.0f;
#pragma unroll
        for (int nt = 0; nt < 8; ++nt) {
            float p0 = __expf(sv[nt][0] - newm_lo);
            float p1 = __expf(sv[nt][1] - newm_lo);
            float p2 = __expf(sv[nt][2] - newm_hi);
            float p3 = __expf(sv[nt][3] - newm_hi);
            rs_lo += p0 + p1;
            rs_hi += p2 + p3;
            sv[nt][0] = p0; sv[nt][1] = p1; sv[nt][2] = p2; sv[nt][3] = p3;
        }
        rs_lo += __shfl_xor_sync(0xffffffffu, rs_lo, 1);
        rs_lo += __shfl_xor_sync(0xffffffffu, rs_lo, 2);
        rs_hi += __shfl_xor_sync(0xffffffffu, rs_hi, 1);
        rs_hi += __shfl_xor_sync(0xffffffffu, rs_hi, 2);
        l_lo = l_lo * alpha_lo + rs_lo;
        l_hi = l_hi * alpha_hi + rs_hi;

        // ---- rescale O ----
#pragma unroll
        for (int nt = 0; nt < 8; ++nt) {
            oacc[nt][0] *= alpha_lo; oacc[nt][1] *= alpha_lo;
            oacc[nt][2] *= alpha_hi; oacc[nt][3] *= alpha_hi;
        }

        // ---- O += P V (S-frag permute + V-row permute) ----
#pragma unroll
        for (int ks = 0; ks < 8; ++ks) {
            uint32_t a0 = f32_to_tf32(sv[ks][0]);
            uint32_t a1 = f32_to_tf32(sv[ks][2]);
            uint32_t a2 = f32_to_tf32(sv[ks][1]);
            uint32_t a3 = f32_to_tf32(sv[ks][3]);
            const int vr0 = ks * 8 + 2 * qc;
#pragma unroll
            for (int nt = 0; nt < 8; ++nt) {
                uint32_t b0 = __float_as_uint(Vs[vr0 * VST + nt * 8 + gr]);
                uint32_t b1 = __float_as_uint(Vs[(vr0 + 1) * VST + nt * 8 + gr]);
                mma_tf32(oacc[nt][0], oacc[nt][1], oacc[nt][2], oacc[nt][3],
                         a0, a1, a2, a3, b0, b1);
            }
        }
    }

    // ---- epilogue ----
    float inv_lo = 1.0f / l_lo;
    float inv_hi = 1.0f / l_hi;
    float* Or0 = Og + base + (size_t)(q0 + wrow + gr) * H_;
    float* Or1 = Og + base + (size_t)(q0 + wrow + gr + 8) * H_;
#pragma unroll
    for (int nt = 0; nt < 8; ++nt) {
        int col = nt * 8 + 2 * qc;
        *(float2*)(Or0 + col) = make_float2(oacc[nt][0] * inv_lo, oacc[nt][1] * inv_lo);
        *(float2*)(Or1 + col) = make_float2(oacc[nt][2] * inv_hi, oacc[nt][3] * inv_hi);
    }
}

// ---------------------------------------------------------------------------
extern "C" void kernel_launch(void* const* d_in, const int* in_sizes, int n_in,
                              void* d_out, int out_size)
{
    const float* query = (const float*)d_in[0];
    const float* key   = (const float*)d_in[1];
    const float* value = (const float*)d_in[2];
    const int*   mask  = (const int*)d_in[3];
    const float* smask = (const float*)d_in[4];
    const float* Wq = (const float*)d_in[5];
    const float* bq = (const float*)d_in[6];
    const float* Wk = (const float*)d_in[7];
    const float* bk = (const float*)d_in[8];
    const float* Wv = (const float*)d_in[9];
    const float* bv = (const float*)d_in[10];
    const float* Wo = (const float*)d_in[11];
    const float* bo = (const float*)d_in[12];
    float* out = (float*)d_out;

    float *gq, *gk, *gv, *gao, *gfm;
    cudaGetSymbolAddress((void**)&gq,  g_Q);
    cudaGetSymbolAddress((void**)&gk,  g_K);
    cudaGetSymbolAddress((void**)&gv,  g_V);
    cudaGetSymbolAddress((void**)&gao, g_AO);
    cudaGetSymbolAddress((void**)&gfm, g_FM);

    cudaFuncSetAttribute(qkv_gemm_kernel,
                         cudaFuncAttributeMaxDynamicSharedMemorySize, G_SMEM_BYTES);
    cudaFuncSetAttribute(out_gemm_kernel,
                         cudaFuncAttributeMaxDynamicSharedMemorySize, G_SMEM_BYTES);
    cudaFuncSetAttribute(attn_mma_kernel,
                         cudaFuncAttributeMaxDynamicSharedMemorySize, ATT_SMEM_BYTES);

    fuse_mask_kernel<<<(B_ * S_ * S_ / 4) / 256, 256>>>(mask, smask, gfm);

    dim3 gblk(256);
    dim3 qkvgrid(H_ / 128, M_ / 128, 3);   // (8, 32, 3)
    qkv_gemm_kernel<<<qkvgrid, gblk, G_SMEM_BYTES>>>(
        query, key, value, Wq, Wk, Wv, bq, bk, bv, gq, gk, gv);

    dim3 agrid(S_ / 128, NH_, B_);         // (16, 16, 2)
    attn_mma_kernel<<<agrid, 256, ATT_SMEM_BYTES>>>(gq, gk, gv, gfm, gao);

    dim3 ogrid(H_ / 128, M_ / 128);        // (8, 32)
    out_gemm_kernel<<<ogrid, gblk, G_SMEM_BYTES>>>(gao, Wo, bo, out);
}